// round 6
// baseline (speedup 1.0000x reference)
#include <cuda_runtime.h>

#define L   32768
#define H   128
#define E   10
#define V   21
#define O   21
#define G3H 384

// Scratch for hidden states (allocation-free rule: __device__ global).
__device__ float g_hiddens[L * H];

typedef unsigned long long u64;

__device__ __forceinline__ u64 pack2(float lo, float hi) {
    u64 r; asm("mov.b64 %0, {%1, %2};" : "=l"(r) : "f"(lo), "f"(hi)); return r;
}
__device__ __forceinline__ void unpack2(u64 v, float& lo, float& hi) {
    asm("mov.b64 {%0, %1}, %2;" : "=f"(lo), "=f"(hi) : "l"(v));
}
// Packed fp32x2 FMA (sm_100+): d = a*b + c elementwise on 2 floats.
__device__ __forceinline__ u64 ffma2(u64 a, u64 b, u64 c) {
    u64 d; asm("fma.rn.f32x2 %0, %1, %2, %3;" : "=l"(d) : "l"(a), "l"(b), "l"(c));
    return d;
}

// ---------------------------------------------------------------------------
// Eigen/XLA-style F32 tanh: rational approx x*P(x2)/Q(x2), Horner with FMA.
// __fdividef: 2-ulp ratio, ~1e-7 abs — invisible through the contractive GRU.
// ---------------------------------------------------------------------------
__device__ __forceinline__ float tanh_xla(float x) {
    const float kBound = 7.90531110763549805f;
    float xc = fminf(fmaxf(x, -kBound), kBound);
    float x2 = xc * xc;
    float p = fmaf(x2, -2.76076847742355e-16f, 2.00018790482477e-13f);
    p = fmaf(x2, p, -8.60467152213735e-11f);
    p = fmaf(x2, p,  5.12229709037114e-08f);
    p = fmaf(x2, p,  1.48572235717979e-05f);
    p = fmaf(x2, p,  6.37261928875436e-04f);
    p = fmaf(x2, p,  4.89352455891786e-03f);
    p = p * xc;
    float q = fmaf(x2,  1.19825839466702e-06f, 1.18534705686654e-04f);
    q = fmaf(x2, q,  2.26843463243900e-03f);
    q = fmaf(x2, q,  4.89352518554385e-03f);
    float r = __fdividef(p, q);
    return (fabsf(x) < 0.0004f) ? x : r;
}
// sigmoid(x) = 0.5 + 0.5 * tanh(0.5 * x)
__device__ __forceinline__ float fsig(float x) {
    return fmaf(0.5f, tanh_xla(0.5f * x), 0.5f);
}

// ---------------------------------------------------------------------------
// Persistent single-CTA GRU. 384 threads; thread j owns row j of W (3H rows).
// W_hh row lives in 64 packed-f32x2 registers; h broadcast from smem.
// ---------------------------------------------------------------------------
__global__ __launch_bounds__(G3H, 1) void gru_kernel(
    const int*   __restrict__ tokens,
    const float* __restrict__ emb,       // [V, E] = [21, 10]
    const float* __restrict__ W_ih,      // [3H, E] = [384, 10]
    const float* __restrict__ W_hh,      // [3H, H] = [384, 128]
    const float* __restrict__ b_ih,
    const float* __restrict__ b_hh,
    float*       __restrict__ out_lasth)
{
    __shared__ float table[V * G3H];                 // x_proj per vocab id
    __shared__ float ghs[G3H];
    __shared__ __align__(16) float hbuf[2][H];       // h ping-pong

    const int j = threadIdx.x;

    if (j < H) { hbuf[0][j] = 0.0f; hbuf[1][j] = 0.0f; }

    // ---- input-projection table: table[v][j] = emb[v] . W_ih[j] + b_ih[j] ----
    {
        float wr[E];
        #pragma unroll
        for (int k = 0; k < E; ++k) wr[k] = W_ih[j * E + k];
        const float bij = b_ih[j];
        for (int v = 0; v < V; ++v) {
            float acc = bij;
            #pragma unroll
            for (int k = 0; k < E; ++k) acc = fmaf(wr[k], emb[v * E + k], acc);
            table[v * G3H + j] = acc;
        }
    }

    // ---- recurrent weights into registers (aligned 8B loads) ----
    u64 w[64];
    {
        const u64* wrow = (const u64*)(W_hh + j * H);
        #pragma unroll
        for (int k = 0; k < 64; ++k) w[k] = wrow[k];
    }
    const float bj = b_hh[j];

    int tok_cur = tokens[0];            // broadcast load, all threads
    __syncthreads();

    // ---- the serial recurrence ----
    for (int t = 0; t < L; ++t) {
        // prefetch next token; completes under the gh phase
        const int tn = (t + 1 < L) ? t + 1 : t;
        const int tok_next = tokens[tn];

        const int ph = t & 1;
        const u64* hc = (const u64*)hbuf[ph];

        // gh[j] = h . W_hh[j] + b_hh[j]   (dual accumulators break RAW chain)
        u64 a0 = pack2(bj, 0.0f), a1 = pack2(0.0f, 0.0f);
        #pragma unroll
        for (int k = 0; k < 64; k += 2) {
            a0 = ffma2(w[k],     hc[k],     a0);
            a1 = ffma2(w[k + 1], hc[k + 1], a1);
        }
        float l0, h0, l1, h1; unpack2(a0, l0, h0); unpack2(a1, l1, h1);
        ghs[j] = (l0 + h0) + (l1 + h1);
        __syncthreads();

        if (j < H) {
            // gate phase (threads 0..127)
            const float* tb = table + tok_cur * G3H;
            const float r  = fsig(tb[j]          + ghs[j]);
            const float z  = fsig(tb[H + j]      + ghs[H + j]);
            const float n  = tanh_xla(tb[2 * H + j] + r * ghs[2 * H + j]);
            const float hv = hbuf[ph][j];
            const float hn = (1.0f - z) * n + z * hv;   // as written in reference
            hbuf[ph ^ 1][j] = hn;
            g_hiddens[t * H + j] = hn;
            if (t == L - 1) out_lasth[j] = hn;
        }
        tok_cur = tok_next;
        __syncthreads();
    }
}

// ---------------------------------------------------------------------------
// Decode: warp per timestep. logits = h_t . W_dec^T + b_dec, then log_softmax.
// W_dec in smem with stride H+1 to kill the 21-way bank conflict.
// ---------------------------------------------------------------------------
#define WDS (H + 1)

__global__ __launch_bounds__(256) void decode_kernel(
    const float* __restrict__ W_dec,
    const float* __restrict__ b_dec,
    float*       __restrict__ out)
{
    __shared__ float wdec[O * WDS];
    __shared__ float bdec[O];
    __shared__ __align__(16) float hb[8][H];

    const int tid = threadIdx.x;
    for (int i = tid; i < O * H; i += 256) wdec[(i / H) * WDS + (i % H)] = W_dec[i];
    if (tid < O) bdec[tid] = b_dec[tid];
    __syncthreads();

    const int warp = tid >> 5, lane = tid & 31;
    const int t = blockIdx.x * 8 + warp;   // grid sized exactly L/8

    // coalesced 512B load of h_t
    const float4 hv = ((const float4*)(g_hiddens + (size_t)t * H))[lane];
    ((float4*)hb[warp])[lane] = hv;
    __syncwarp();

    float logit = -1e30f;
    if (lane < O) {
        const float* wr = wdec + lane * WDS;
        const float* hh = hb[warp];
        float acc = bdec[lane];
        #pragma unroll
        for (int k = 0; k < H; ++k) acc = fmaf(wr[k], hh[k], acc);
        logit = acc;
    }
    float m = logit;
    #pragma unroll
    for (int o = 16; o; o >>= 1) m = fmaxf(m, __shfl_xor_sync(0xffffffffu, m, o));
    float e = (lane < O) ? expf(logit - m) : 0.0f;
    float s = e;
    #pragma unroll
    for (int o = 16; o; o >>= 1) s += __shfl_xor_sync(0xffffffffu, s, o);
    if (lane < O) out[(size_t)t * O + lane] = logit - m - logf(s);
}

extern "C" void kernel_launch(void* const* d_in, const int* in_sizes, int n_in,
                              void* d_out, int out_size)
{
    const int*   tokens = (const int*)  d_in[0];
    const float* emb    = (const float*)d_in[1];
    const float* W_ih   = (const float*)d_in[2];
    const float* W_hh   = (const float*)d_in[3];
    const float* b_ih   = (const float*)d_in[4];
    const float* b_hh   = (const float*)d_in[5];
    const float* W_dec  = (const float*)d_in[6];
    const float* b_dec  = (const float*)d_in[7];
    float* out = (float*)d_out;

    // output layout: [L*O] log_softmax, then [H] last hidden
    gru_kernel<<<1, G3H>>>(tokens, emb, W_ih, W_hh, b_ih, b_hh,
                           out + (size_t)L * O);
    decode_kernel<<<L / 8, 256>>>(W_dec, b_dec, out);
}

// round 7
// speedup vs baseline: 1.0020x; 1.0020x over previous
#include <cuda_runtime.h>

#define L   32768
#define H   128
#define E   10
#define V   21
#define O   21
#define G3H 384

// Scratch for hidden states (allocation-free rule: __device__ global).
__device__ float g_hiddens[L * H];

typedef unsigned long long u64;

__device__ __forceinline__ u64 pack2(float lo, float hi) {
    u64 r; asm("mov.b64 %0, {%1, %2};" : "=l"(r) : "f"(lo), "f"(hi)); return r;
}
__device__ __forceinline__ void unpack2(u64 v, float& lo, float& hi) {
    asm("mov.b64 {%0, %1}, %2;" : "=f"(lo), "=f"(hi) : "l"(v));
}
// Packed fp32x2 FMA (sm_100+): d = a*b + c elementwise on 2 floats.
__device__ __forceinline__ u64 ffma2(u64 a, u64 b, u64 c) {
    u64 d; asm("fma.rn.f32x2 %0, %1, %2, %3;" : "=l"(d) : "l"(a), "l"(b), "l"(c));
    return d;
}

// ---------------------------------------------------------------------------
// Eigen/XLA-style F32 tanh: rational approx x*P(x2)/Q(x2), Horner with FMA.
// ---------------------------------------------------------------------------
__device__ __forceinline__ float tanh_xla(float x) {
    const float kBound = 7.90531110763549805f;
    float xc = fminf(fmaxf(x, -kBound), kBound);
    float x2 = xc * xc;
    float p = fmaf(x2, -2.76076847742355e-16f, 2.00018790482477e-13f);
    p = fmaf(x2, p, -8.60467152213735e-11f);
    p = fmaf(x2, p,  5.12229709037114e-08f);
    p = fmaf(x2, p,  1.48572235717979e-05f);
    p = fmaf(x2, p,  6.37261928875436e-04f);
    p = fmaf(x2, p,  4.89352455891786e-03f);
    p = p * xc;
    float q = fmaf(x2,  1.19825839466702e-06f, 1.18534705686654e-04f);
    q = fmaf(x2, q,  2.26843463243900e-03f);
    q = fmaf(x2, q,  4.89352518554385e-03f);
    float r = __fdividef(p, q);
    return (fabsf(x) < 0.0004f) ? x : r;
}
// sigmoid(x) = 0.5 + 0.5 * tanh(0.5 * x)
__device__ __forceinline__ float fsig(float x) {
    return fmaf(0.5f, tanh_xla(0.5f * x), 0.5f);
}

// ---------------------------------------------------------------------------
// Persistent single-CTA GRU. 384 threads; thread j owns row j of W (3H rows).
// W_hh row register-resident as 64 packed f32x2; h broadcast from smem via
// LDS.128 (16B) to halve the per-step LDS wavefront count.
// ---------------------------------------------------------------------------
__global__ __launch_bounds__(G3H, 1) void gru_kernel(
    const int*   __restrict__ tokens,
    const float* __restrict__ emb,       // [V, E] = [21, 10]
    const float* __restrict__ W_ih,      // [3H, E] = [384, 10]
    const float* __restrict__ W_hh,      // [3H, H] = [384, 128]
    const float* __restrict__ b_ih,
    const float* __restrict__ b_hh,
    float*       __restrict__ out_lasth)
{
    __shared__ float table[V * G3H];                 // x_proj per vocab id
    __shared__ float ghs[G3H];
    __shared__ __align__(16) float hbuf[2][H];       // h ping-pong

    const int j = threadIdx.x;

    if (j < H) { hbuf[0][j] = 0.0f; hbuf[1][j] = 0.0f; }

    // ---- input-projection table: table[v][j] = emb[v] . W_ih[j] + b_ih[j] ----
    {
        float wr[E];
        #pragma unroll
        for (int k = 0; k < E; ++k) wr[k] = W_ih[j * E + k];
        const float bij = b_ih[j];
        for (int v = 0; v < V; ++v) {
            float acc = bij;
            #pragma unroll
            for (int k = 0; k < E; ++k) acc = fmaf(wr[k], emb[v * E + k], acc);
            table[v * G3H + j] = acc;
        }
    }

    // ---- recurrent weights into registers (aligned 8B loads) ----
    u64 w[64];
    {
        const u64* wrow = (const u64*)(W_hh + j * H);
        #pragma unroll
        for (int k = 0; k < 64; ++k) w[k] = wrow[k];
    }
    const float bj = b_hh[j];

    int tok_cur = tokens[0];            // broadcast load, all threads
    __syncthreads();

    // ---- the serial recurrence ----
    for (int t = 0; t < L; ++t) {
        // prefetch next token; completes under the gh phase
        const int tn = (t + 1 < L) ? t + 1 : t;
        const int tok_next = tokens[tn];

        const int ph = t & 1;

        // Prefetch gate-phase operands early so their LDS latency hides
        // under the dot phase (warps 0-3 only).
        float tb0 = 0.f, tb1 = 0.f, tb2 = 0.f, hv = 0.f;
        if (j < H) {
            const float* tb = table + tok_cur * G3H;
            tb0 = tb[j]; tb1 = tb[H + j]; tb2 = tb[2 * H + j];
            hv  = hbuf[ph][j];
        }

        // gh[j] = h . W_hh[j] + b_hh[j]; h read 16B at a time (LDS.128),
        // dual packed accumulators break the RAW chain.
        const float4* hc4 = (const float4*)hbuf[ph];
        u64 a0 = pack2(bj, 0.0f), a1 = pack2(0.0f, 0.0f);
        #pragma unroll
        for (int q = 0; q < 32; q += 2) {
            const float4 v0 = hc4[q];
            const float4 v1 = hc4[q + 1];
            a0 = ffma2(w[2 * q],     pack2(v0.x, v0.y), a0);
            a1 = ffma2(w[2 * q + 1], pack2(v0.z, v0.w), a1);
            a0 = ffma2(w[2 * q + 2], pack2(v1.x, v1.y), a0);
            a1 = ffma2(w[2 * q + 3], pack2(v1.z, v1.w), a1);
        }
        float l0, h0, l1, h1; unpack2(a0, l0, h0); unpack2(a1, l1, h1);
        ghs[j] = (l0 + h0) + (l1 + h1);
        __syncthreads();

        if (j < H) {
            // gate phase (threads 0..127); tb*/hv already in registers
            const float r  = fsig(tb0 + ghs[j]);
            const float z  = fsig(tb1 + ghs[H + j]);
            const float n  = tanh_xla(tb2 + r * ghs[2 * H + j]);
            const float hn = (1.0f - z) * n + z * hv;   // as written in reference
            hbuf[ph ^ 1][j] = hn;
            g_hiddens[t * H + j] = hn;
            if (t == L - 1) out_lasth[j] = hn;
        }
        tok_cur = tok_next;
        __syncthreads();
    }
}

// ---------------------------------------------------------------------------
// Decode: warp per timestep. logits = h_t . W_dec^T + b_dec, then log_softmax.
// W_dec in smem with stride H+1 to kill the 21-way bank conflict.
// ---------------------------------------------------------------------------
#define WDS (H + 1)

__global__ __launch_bounds__(256) void decode_kernel(
    const float* __restrict__ W_dec,
    const float* __restrict__ b_dec,
    float*       __restrict__ out)
{
    __shared__ float wdec[O * WDS];
    __shared__ float bdec[O];
    __shared__ __align__(16) float hb[8][H];

    const int tid = threadIdx.x;
    for (int i = tid; i < O * H; i += 256) wdec[(i / H) * WDS + (i % H)] = W_dec[i];
    if (tid < O) bdec[tid] = b_dec[tid];
    __syncthreads();

    const int warp = tid >> 5, lane = tid & 31;
    const int t = blockIdx.x * 8 + warp;   // grid sized exactly L/8

    // coalesced 512B load of h_t
    const float4 hv = ((const float4*)(g_hiddens + (size_t)t * H))[lane];
    ((float4*)hb[warp])[lane] = hv;
    __syncwarp();

    float logit = -1e30f;
    if (lane < O) {
        const float* wr = wdec + lane * WDS;
        const float* hh = hb[warp];
        float acc = bdec[lane];
        #pragma unroll
        for (int k = 0; k < H; ++k) acc = fmaf(wr[k], hh[k], acc);
        logit = acc;
    }
    float m = logit;
    #pragma unroll
    for (int o = 16; o; o >>= 1) m = fmaxf(m, __shfl_xor_sync(0xffffffffu, m, o));
    float e = (lane < O) ? expf(logit - m) : 0.0f;
    float s = e;
    #pragma unroll
    for (int o = 16; o; o >>= 1) s += __shfl_xor_sync(0xffffffffu, s, o);
    if (lane < O) out[(size_t)t * O + lane] = logit - m - logf(s);
}

extern "C" void kernel_launch(void* const* d_in, const int* in_sizes, int n_in,
                              void* d_out, int out_size)
{
    const int*   tokens = (const int*)  d_in[0];
    const float* emb    = (const float*)d_in[1];
    const float* W_ih   = (const float*)d_in[2];
    const float* W_hh   = (const float*)d_in[3];
    const float* b_ih   = (const float*)d_in[4];
    const float* b_hh   = (const float*)d_in[5];
    const float* W_dec  = (const float*)d_in[6];
    const float* b_dec  = (const float*)d_in[7];
    float* out = (float*)d_out;

    // output layout: [L*O] log_softmax, then [H] last hidden
    gru_kernel<<<1, G3H>>>(tokens, emb, W_ih, W_hh, b_ih, b_hh,
                           out + (size_t)L * O);
    decode_kernel<<<L / 8, 256>>>(W_dec, b_dec, out);
}